// round 4
// baseline (speedup 1.0000x reference)
#include <cuda_runtime.h>
#include <cuda_bf16.h>
#include <math.h>

// ---------------- static scratch (no allocations allowed) ----------------
#define MAXN 100000
#define MAXE 1600000
#define NGRAPH 256

__device__ float g_bufA[(size_t)MAXN * 64];  // ping (N x 64)
__device__ float g_bufB[(size_t)MAXN * 64];  // pong (N x 64)
__device__ float g_xs[(size_t)MAXN * 5];     // prescaled input features
__device__ int   g_cnt[MAXN];
__device__ int   g_rowptr[MAXN + 1];
__device__ int   g_curoff[MAXN];
__device__ float g_dinv[MAXN];
__device__ int   g_col[MAXE];
__device__ int   g_bsums[128];
__device__ float g_pool[NGRAPH * 64];
__device__ float g_gcnt[NGRAPH];
__device__ int   g_is64[1];   // 1 if index arrays are int64, 0 if int32

__device__ __forceinline__ int load_idx(const void* p, long long i, int is64) {
    if (is64) return (int)((const long long*)p)[i];
    return ((const int*)p)[i];
}

// ---------------- init (+ dtype detect in block 0) ----------------
__global__ void k_init(int* cnt, float* pool, float* gcnt, int n,
                       const int* __restrict__ eprobe, int* flag) {
    int i = blockIdx.x * blockDim.x + threadIdx.x;
    if (i < n) cnt[i] = 0;
    if (i < NGRAPH * 64) pool[i] = 0.f;
    if (i < NGRAPH) gcnt[i] = 0.f;
    if (blockIdx.x == 0) {
        __shared__ int any;
        if (threadIdx.x == 0) any = 0;
        __syncthreads();
        int loc = 0;
        for (int q = threadIdx.x; q < 512; q += blockDim.x)
            if (eprobe[2 * q + 1] != 0) loc = 1;
        if (loc) atomicOr(&any, 1);
        __syncthreads();
        if (threadIdx.x == 0) flag[0] = any ? 0 : 1;
    }
}

// ---------------- degree count ----------------
__global__ void k_count(const void* __restrict__ ei, int E, int* cnt, const int* flag) {
    int is64 = flag[0];
    int e = blockIdx.x * blockDim.x + threadIdx.x;
    if (e < E) {
        int d = load_idx(ei, (long long)E + e, is64);
        atomicAdd(&cnt[d], 1);
    }
}

// ---------------- exclusive scan ----------------
__global__ void k_scan1(const int* __restrict__ cnt, int* rowptr, int* bsums, int n) {
    __shared__ int s[1024];
    int i = blockIdx.x * 1024 + threadIdx.x;
    int v = (i < n) ? cnt[i] : 0;
    s[threadIdx.x] = v;
    __syncthreads();
    for (int off = 1; off < 1024; off <<= 1) {
        int t = 0;
        if ((int)threadIdx.x >= off) t = s[threadIdx.x - off];
        __syncthreads();
        s[threadIdx.x] += t;
        __syncthreads();
    }
    if (i < n) rowptr[i] = s[threadIdx.x] - v;
    if (threadIdx.x == 1023) bsums[blockIdx.x] = s[1023];
}

// parallel block-sum scan (nb <= 128)
__global__ void k_scan2(int* bsums, int nb) {
    int t = threadIdx.x;
    int v = (t < nb) ? bsums[t] : 0;
    int orig = v;
#pragma unroll
    for (int off = 1; off < 32; off <<= 1) {
        int u = __shfl_up_sync(0xffffffffu, v, off);
        if ((t & 31) >= off) v += u;
    }
    __shared__ int ws[4];
    if ((t & 31) == 31) ws[t >> 5] = v;
    __syncthreads();
    if (t == 0) { int a = 0; for (int i = 0; i < 4; i++) { int x = ws[i]; ws[i] = a; a += x; } }
    __syncthreads();
    v += ws[t >> 5];
    if (t < nb) bsums[t] = v - orig; // exclusive
}

// scan finalize + dinv + x prescale (fused)
__global__ void k_scan3(int* rowptr, int* curoff, const int* __restrict__ bsums,
                        const int* __restrict__ cnt, float* dinv,
                        const float* __restrict__ x, float* xs, int n, int E) {
    int i = blockIdx.x * blockDim.x + threadIdx.x;
    if (i < n) {
        int r = rowptr[i] + bsums[i >> 10];
        rowptr[i] = r;
        curoff[i] = r;
        float d = rsqrtf((float)cnt[i] + 1.0f); // +1 self loop
        dinv[i] = d;
#pragma unroll
        for (int k = 0; k < 5; k++) xs[(size_t)i * 5 + k] = d * x[(size_t)i * 5 + k];
    }
    if (i == 0) rowptr[n] = E;
}

// ---------------- CSR fill (col only) ----------------
__global__ void k_fill(const void* __restrict__ ei, int E,
                       int* curoff, int* col, const int* flag) {
    int is64 = flag[0];
    int e = blockIdx.x * blockDim.x + threadIdx.x;
    if (e >= E) return;
    int s = load_idx(ei, e, is64);
    int d = load_idx(ei, (long long)E + e, is64);
    int p = atomicAdd(&curoff[d], 1);
    col[p] = s;
}

// ---------------- fused layer1: agg(xs) + GEMM(5->64) + relu + prescale ------
__global__ void k_l1(const float* __restrict__ xs,
                     const int* __restrict__ rowptr, const int* __restrict__ col,
                     const float* __restrict__ dinv,
                     const float* __restrict__ W1, const float* __restrict__ b1,
                     float* __restrict__ out, int n) {
    __shared__ float Ws[5 * 64];
    __shared__ float bs[64];
    int t = threadIdx.x;
    for (int i = t; i < 5 * 64; i += 256) Ws[i] = W1[i];
    if (t < 64) bs[t] = b1[t];
    __syncthreads();

    int gt = blockIdx.x * 256 + t;
    int node = gt >> 3;
    int f = gt & 7;
    bool live = (node < n);
    int nodec = live ? node : (n - 1);

    int beg = rowptr[nodec], end = rowptr[nodec + 1];
    bool valid = (f < 5);
    float acc = 0.f;
    for (int e = beg; e < end; e++) {
        int s = col[e];
        if (valid) acc += __ldg(&xs[(size_t)s * 5 + f]);
    }
    float ds = dinv[nodec];
    if (valid) acc = ds * (acc + xs[(size_t)nodec * 5 + f]);

    float v[5];
#pragma unroll
    for (int k = 0; k < 5; k++) v[k] = __shfl_sync(0xffffffffu, acc, k, 8);

    int cb = f * 8;
    float o[8];
#pragma unroll
    for (int j = 0; j < 8; j++) {
        float a = bs[cb + j];
#pragma unroll
        for (int k = 0; k < 5; k++) a += v[k] * Ws[k * 64 + cb + j];
        o[j] = fmaxf(a, 0.f) * ds;     // prescale for next aggregation
    }
    if (live) {
        float4* p = reinterpret_cast<float4*>(&out[(size_t)node * 64 + cb]);
        p[0] = make_float4(o[0], o[1], o[2], o[3]);
        p[1] = make_float4(o[4], o[5], o[6], o[7]);
    }
}

// ---------------- aggregation width 64: float4 gathers, no weights ----------
// h is pre-scaled by dinv[src]. result = dinv[dst]*(sum gathered + self).
template <bool POOL>
__global__ void k_agg64(const float* __restrict__ h,
                        const int* __restrict__ rowptr, const int* __restrict__ col,
                        const float* __restrict__ dinv,
                        const float* __restrict__ bias,
                        const void* __restrict__ batch, const int* flag,
                        float* __restrict__ out, float* pool, float* gcnt, int n) {
    int node = blockIdx.x * 8 + (threadIdx.x >> 5);
    int lane = threadIdx.x & 31;
    if (node >= n) return;
    int half = lane >> 4;
    int q = lane & 15;
    int beg = rowptr[node], end = rowptr[node + 1];
    float4 acc = make_float4(0.f, 0.f, 0.f, 0.f);
    int e = beg + half;
    for (; e + 2 < end; e += 4) {
        int s0 = col[e], s1 = col[e + 2];
        float4 v0 = __ldg(reinterpret_cast<const float4*>(h + (size_t)s0 * 64) + q);
        float4 v1 = __ldg(reinterpret_cast<const float4*>(h + (size_t)s1 * 64) + q);
        acc.x += v0.x + v1.x; acc.y += v0.y + v1.y;
        acc.z += v0.z + v1.z; acc.w += v0.w + v1.w;
    }
    for (; e < end; e += 2) {
        int s = col[e];
        float4 v = __ldg(reinterpret_cast<const float4*>(h + (size_t)s * 64) + q);
        acc.x += v.x; acc.y += v.y; acc.z += v.z; acc.w += v.w;
    }
    acc.x += __shfl_xor_sync(0xffffffffu, acc.x, 16);
    acc.y += __shfl_xor_sync(0xffffffffu, acc.y, 16);
    acc.z += __shfl_xor_sync(0xffffffffu, acc.z, 16);
    acc.w += __shfl_xor_sync(0xffffffffu, acc.w, 16);
    if (half == 0) {
        float4 self = *(reinterpret_cast<const float4*>(h + (size_t)node * 64) + q);
        float ds = dinv[node];
        float r0 = ds * (acc.x + self.x);
        float r1 = ds * (acc.y + self.y);
        float r2 = ds * (acc.z + self.z);
        float r3 = ds * (acc.w + self.w);
        if (POOL) {
            float4 b = __ldg(reinterpret_cast<const float4*>(bias) + q);
            r0 = fmaxf(r0 + b.x, 0.f);
            r1 = fmaxf(r1 + b.y, 0.f);
            r2 = fmaxf(r2 + b.z, 0.f);
            r3 = fmaxf(r3 + b.w, 0.f);
            int g = load_idx(batch, node, flag[0]);
            float* pp = &pool[g * 64 + q * 4];
            atomicAdd(pp + 0, r0);
            atomicAdd(pp + 1, r1);
            atomicAdd(pp + 2, r2);
            atomicAdd(pp + 3, r3);
            if (lane == 0) atomicAdd(&gcnt[g], 1.0f);
        } else {
            *(reinterpret_cast<float4*>(out + (size_t)node * 64) + q) =
                make_float4(r0, r1, r2, r3);
        }
    }
}

// ---------------- fused GEMM2+GEMM3: t(Nx64) -> relu(t@W2+b2)@W3 * dinv ------
// dynamic smem: [W2s 32KB][W3s 32KB][U: As 16KB then H2s 33.8KB]
#define G23_SMEM (32768 + 32768 + 64 * 132 * 4)
__launch_bounds__(256)
__global__ void k_gemm23(const float* __restrict__ T, const float* __restrict__ W2,
                         const float* __restrict__ b2, const float* __restrict__ W3,
                         const float* __restrict__ dinv, float* __restrict__ out, int n) {
    extern __shared__ float sm[];
    float* W2s = sm;                  // [64][128]
    float* W3s = sm + 8192;           // [128][64]
    float* U   = sm + 16384;          // As [64][64] then H2s [64][132]
    const int t = threadIdx.x;
    const int tx = t & 15;
    const int ty = t >> 4;
    const int nodeBase = blockIdx.x * 64;

    // load W2, W3 (float4)
    for (int q = t; q < 2048; q += 256)
        reinterpret_cast<float4*>(W2s)[q] = reinterpret_cast<const float4*>(W2)[q];
    for (int q = t; q < 2048; q += 256)
        reinterpret_cast<float4*>(W3s)[q] = reinterpret_cast<const float4*>(W3)[q];
    // load A tile transposed: As[k][node]
    for (int q = t; q < 1024; q += 256) {
        int node = q >> 4;
        int kk4 = (q & 15) * 4;
        int gn = nodeBase + node;
        float4 v = make_float4(0.f, 0.f, 0.f, 0.f);
        if (gn < n) v = *reinterpret_cast<const float4*>(&T[(size_t)gn * 64 + kk4]);
        U[(kk4 + 0) * 64 + node] = v.x;
        U[(kk4 + 1) * 64 + node] = v.y;
        U[(kk4 + 2) * 64 + node] = v.z;
        U[(kk4 + 3) * 64 + node] = v.w;
    }
    float br[8];
#pragma unroll
    for (int j = 0; j < 8; j++) br[j] = __ldg(&b2[tx * 8 + j]);
    __syncthreads();

    // stage 1: h2 = relu(A@W2 + b2), microtile 4 nodes x 8 cols
    float acc1[4][8];
#pragma unroll
    for (int i = 0; i < 4; i++)
#pragma unroll
        for (int j = 0; j < 8; j++) acc1[i][j] = 0.f;
#pragma unroll 4
    for (int k = 0; k < 64; k++) {
        float4 av = *reinterpret_cast<const float4*>(&U[k * 64 + ty * 4]);
        float a4[4] = {av.x, av.y, av.z, av.w};
        float4 b0 = *reinterpret_cast<const float4*>(&W2s[k * 128 + tx * 8]);
        float4 b1 = *reinterpret_cast<const float4*>(&W2s[k * 128 + tx * 8 + 4]);
        float bv[8] = {b0.x, b0.y, b0.z, b0.w, b1.x, b1.y, b1.z, b1.w};
#pragma unroll
        for (int i = 0; i < 4; i++)
#pragma unroll
            for (int j = 0; j < 8; j++) acc1[i][j] += a4[i] * bv[j];
    }
    __syncthreads();   // As reads done; U becomes H2s [node][132]
#pragma unroll
    for (int i = 0; i < 4; i++)
#pragma unroll
        for (int j = 0; j < 8; j++)
            U[(ty * 4 + i) * 132 + tx * 8 + j] = fmaxf(acc1[i][j] + br[j], 0.f);
    __syncthreads();

    // stage 2: out = (H2 @ W3) * dinv, microtile 4 nodes x 4 cols
    float acc2[4][4];
#pragma unroll
    for (int i = 0; i < 4; i++)
#pragma unroll
        for (int j = 0; j < 4; j++) acc2[i][j] = 0.f;
#pragma unroll 2
    for (int k = 0; k < 128; k++) {
        float a0 = U[(ty * 4 + 0) * 132 + k];
        float a1 = U[(ty * 4 + 1) * 132 + k];
        float a2 = U[(ty * 4 + 2) * 132 + k];
        float a3 = U[(ty * 4 + 3) * 132 + k];
        float4 w4 = *reinterpret_cast<const float4*>(&W3s[k * 64 + tx * 4]);
        float wv[4] = {w4.x, w4.y, w4.z, w4.w};
        float aa[4] = {a0, a1, a2, a3};
#pragma unroll
        for (int i = 0; i < 4; i++)
#pragma unroll
            for (int j = 0; j < 4; j++) acc2[i][j] += aa[i] * wv[j];
    }
#pragma unroll
    for (int i = 0; i < 4; i++) {
        int gn = nodeBase + ty * 4 + i;
        if (gn < n) {
            float ds = dinv[gn];
            *reinterpret_cast<float4*>(&out[(size_t)gn * 64 + tx * 4]) =
                make_float4(acc2[i][0] * ds, acc2[i][1] * ds,
                            acc2[i][2] * ds, acc2[i][3] * ds);
        }
    }
}

// ---------------- final FC + sigmoid ----------------
__global__ void k_final(const float* __restrict__ pool, const float* __restrict__ gcnt,
                        const float* __restrict__ Wfc, const float* __restrict__ bfc,
                        float* __restrict__ out) {
    int g = threadIdx.x;
    float c = fmaxf(gcnt[g], 1.0f);
    float acc = 0.f;
#pragma unroll
    for (int k = 0; k < 64; k++) acc += pool[g * 64 + k] * Wfc[k];
    acc = acc / c + bfc[0];
    out[g] = 1.f / (1.f + expf(-acc));
}

// ---------------- launch ----------------
extern "C" void kernel_launch(void* const* d_in, const int* in_sizes, int n_in,
                              void* d_out, int out_size) {
    const float*  x     = (const float*)d_in[0];
    const void*   ei    = d_in[1];
    const void*   batch = d_in[2];
    const float*  W1    = (const float*)d_in[3];
    const float*  b1    = (const float*)d_in[4];
    const float*  W2    = (const float*)d_in[5];
    const float*  b2    = (const float*)d_in[6];
    const float*  W3    = (const float*)d_in[7];
    const float*  b3    = (const float*)d_in[8];
    const float*  Wfc   = (const float*)d_in[9];
    const float*  bfc   = (const float*)d_in[10];
    float*        out   = (float*)d_out;

    const int N = in_sizes[0] / 5;
    const int E = in_sizes[1] / 2;

    float *bufA, *bufB, *xs, *dinv, *pool, *gcnt;
    int *cnt, *rowptr, *curoff, *col, *bsums, *is64;
    cudaGetSymbolAddress((void**)&bufA, g_bufA);
    cudaGetSymbolAddress((void**)&bufB, g_bufB);
    cudaGetSymbolAddress((void**)&xs, g_xs);
    cudaGetSymbolAddress((void**)&dinv, g_dinv);
    cudaGetSymbolAddress((void**)&pool, g_pool);
    cudaGetSymbolAddress((void**)&gcnt, g_gcnt);
    cudaGetSymbolAddress((void**)&cnt, g_cnt);
    cudaGetSymbolAddress((void**)&rowptr, g_rowptr);
    cudaGetSymbolAddress((void**)&curoff, g_curoff);
    cudaGetSymbolAddress((void**)&col, g_col);
    cudaGetSymbolAddress((void**)&bsums, g_bsums);
    cudaGetSymbolAddress((void**)&is64, g_is64);

    static int smem_set = 0;
    if (!smem_set) {
        cudaFuncSetAttribute(k_gemm23, cudaFuncAttributeMaxDynamicSharedMemorySize, G23_SMEM);
        smem_set = 1;
    }

    const int TB = 256;
    int initN = N > NGRAPH * 64 ? N : NGRAPH * 64;
    k_init<<<(initN + TB - 1) / TB, TB>>>(cnt, pool, gcnt, N, (const int*)ei, is64);
    k_count<<<(E + TB - 1) / TB, TB>>>(ei, E, cnt, is64);

    int nb = (N + 1023) / 1024;
    k_scan1<<<nb, 1024>>>(cnt, rowptr, bsums, N);
    k_scan2<<<1, 128>>>(bsums, nb);
    k_scan3<<<(N + TB - 1) / TB, TB>>>(rowptr, curoff, bsums, cnt, dinv, x, xs, N, E);
    k_fill<<<(E + TB - 1) / TB, TB>>>(ei, E, curoff, col, is64);

    // L1 fused: agg5 + GEMM(5->64) + relu, output prescaled by dinv -> bufA
    k_l1<<<(N * 8 + TB - 1) / TB, TB>>>(xs, rowptr, col, dinv, W1, b1, bufA, N);

    // L2 agg (pure adds) -> bufB
    k_agg64<false><<<(N + 7) / 8, TB>>>(bufA, rowptr, col, dinv, nullptr,
                                        nullptr, is64, bufB, nullptr, nullptr, N);
    // fused GEMM2+relu+GEMM3, epilogue * dinv -> bufA
    k_gemm23<<<(N + 63) / 64, TB, G23_SMEM>>>(bufB, W2, b2, W3, dinv, bufA, N);

    // L3 agg + bias + relu + mean-pool (fused)
    k_agg64<true><<<(N + 7) / 8, TB>>>(bufA, rowptr, col, dinv, b3,
                                       batch, is64, nullptr, pool, gcnt, N);

    k_final<<<1, NGRAPH>>>(pool, gcnt, Wfc, bfc, out);
}

// round 5
// speedup vs baseline: 1.1230x; 1.1230x over previous
#include <cuda_runtime.h>
#include <cuda_bf16.h>
#include <math.h>

// ---------------- static scratch (no allocations allowed) ----------------
#define MAXN 100000
#define MAXE 1600000
#define NGRAPH 256

__device__ float g_bufA[(size_t)MAXN * 128]; // ping (up to N x 128)
__device__ float g_bufB[(size_t)MAXN * 64];  // pong (N x 64)
__device__ float g_xs[(size_t)MAXN * 5];     // prescaled input features
__device__ int   g_cnt[MAXN];
__device__ int   g_rowptr[MAXN + 1];
__device__ int   g_curoff[MAXN];
__device__ float g_dinv[MAXN];
__device__ int   g_col[MAXE];
__device__ int   g_bsums[128];
__device__ float g_pool[NGRAPH * 64];
__device__ float g_gcnt[NGRAPH];
__device__ int   g_is64[1];

__device__ __forceinline__ int load_idx(const void* p, long long i, int is64) {
    if (is64) return (int)((const long long*)p)[i];
    return ((const int*)p)[i];
}

// ---------------- init (+ dtype detect in block 0) ----------------
__global__ void k_init(int* cnt, float* pool, float* gcnt, int n,
                       const int* __restrict__ eprobe, int* flag) {
    int i = blockIdx.x * blockDim.x + threadIdx.x;
    if (i < n) cnt[i] = 0;
    if (i < NGRAPH * 64) pool[i] = 0.f;
    if (i < NGRAPH) gcnt[i] = 0.f;
    if (blockIdx.x == 0) {
        __shared__ int any;
        if (threadIdx.x == 0) any = 0;
        __syncthreads();
        int loc = 0;
        for (int q = threadIdx.x; q < 512; q += blockDim.x)
            if (eprobe[2 * q + 1] != 0) loc = 1;
        if (loc) atomicOr(&any, 1);
        __syncthreads();
        if (threadIdx.x == 0) flag[0] = any ? 0 : 1;
    }
}

// ---------------- degree count ----------------
__global__ void k_count(const void* __restrict__ ei, int E, int* cnt, const int* flag) {
    int is64 = flag[0];
    int e = blockIdx.x * blockDim.x + threadIdx.x;
    if (e < E) {
        int d = load_idx(ei, (long long)E + e, is64);
        atomicAdd(&cnt[d], 1);
    }
}

// ---------------- exclusive scan ----------------
__global__ void k_scan1(const int* __restrict__ cnt, int* rowptr, int* bsums, int n) {
    __shared__ int s[1024];
    int i = blockIdx.x * 1024 + threadIdx.x;
    int v = (i < n) ? cnt[i] : 0;
    s[threadIdx.x] = v;
    __syncthreads();
    for (int off = 1; off < 1024; off <<= 1) {
        int t = 0;
        if ((int)threadIdx.x >= off) t = s[threadIdx.x - off];
        __syncthreads();
        s[threadIdx.x] += t;
        __syncthreads();
    }
    if (i < n) rowptr[i] = s[threadIdx.x] - v;
    if (threadIdx.x == 1023) bsums[blockIdx.x] = s[1023];
}

__global__ void k_scan2(int* bsums, int nb) {
    int t = threadIdx.x;
    int v = (t < nb) ? bsums[t] : 0;
    int orig = v;
#pragma unroll
    for (int off = 1; off < 32; off <<= 1) {
        int u = __shfl_up_sync(0xffffffffu, v, off);
        if ((t & 31) >= off) v += u;
    }
    __shared__ int ws[4];
    if ((t & 31) == 31) ws[t >> 5] = v;
    __syncthreads();
    if (t == 0) { int a = 0; for (int i = 0; i < 4; i++) { int x = ws[i]; ws[i] = a; a += x; } }
    __syncthreads();
    v += ws[t >> 5];
    if (t < nb) bsums[t] = v - orig;
}

// scan finalize + dinv + x prescale (fused)
__global__ void k_scan3(int* rowptr, int* curoff, const int* __restrict__ bsums,
                        const int* __restrict__ cnt, float* dinv,
                        const float* __restrict__ x, float* xs, int n, int E) {
    int i = blockIdx.x * blockDim.x + threadIdx.x;
    if (i < n) {
        int r = rowptr[i] + bsums[i >> 10];
        rowptr[i] = r;
        curoff[i] = r;
        float d = rsqrtf((float)cnt[i] + 1.0f);
        dinv[i] = d;
#pragma unroll
        for (int k = 0; k < 5; k++) xs[(size_t)i * 5 + k] = d * x[(size_t)i * 5 + k];
    }
    if (i == 0) rowptr[n] = E;
}

// ---------------- CSR fill (col only, no weights) ----------------
__global__ void k_fill(const void* __restrict__ ei, int E,
                       int* curoff, int* col, const int* flag) {
    int is64 = flag[0];
    int e = blockIdx.x * blockDim.x + threadIdx.x;
    if (e >= E) return;
    int s = load_idx(ei, e, is64);
    int d = load_idx(ei, (long long)E + e, is64);
    int p = atomicAdd(&curoff[d], 1);
    col[p] = s;
}

// ---------------- fused layer1: agg(xs) + GEMM(5->64) + relu + prescale ------
__global__ void k_l1(const float* __restrict__ xs,
                     const int* __restrict__ rowptr, const int* __restrict__ col,
                     const float* __restrict__ dinv,
                     const float* __restrict__ W1, const float* __restrict__ b1,
                     float* __restrict__ out, int n) {
    __shared__ float Ws[5 * 64];
    __shared__ float bs[64];
    int t = threadIdx.x;
    for (int i = t; i < 5 * 64; i += 256) Ws[i] = W1[i];
    if (t < 64) bs[t] = b1[t];
    __syncthreads();

    int gt = blockIdx.x * 256 + t;
    int node = gt >> 3;
    int f = gt & 7;
    bool live = (node < n);
    int nodec = live ? node : (n - 1);

    int beg = rowptr[nodec], end = rowptr[nodec + 1];
    bool valid = (f < 5);
    float acc = 0.f;
    for (int e = beg; e < end; e++) {
        int s = col[e];
        if (valid) acc += __ldg(&xs[(size_t)s * 5 + f]);
    }
    float ds = dinv[nodec];
    if (valid) acc = ds * (acc + xs[(size_t)nodec * 5 + f]);

    float v[5];
#pragma unroll
    for (int k = 0; k < 5; k++) v[k] = __shfl_sync(0xffffffffu, acc, k, 8);

    int cb = f * 8;
    float o[8];
#pragma unroll
    for (int j = 0; j < 8; j++) {
        float a = bs[cb + j];
#pragma unroll
        for (int k = 0; k < 5; k++) a += v[k] * Ws[k * 64 + cb + j];
        o[j] = fmaxf(a, 0.f) * ds;     // prescale for next aggregation
    }
    if (live) {
        float4* p = reinterpret_cast<float4*>(&out[(size_t)node * 64 + cb]);
        p[0] = make_float4(o[0], o[1], o[2], o[3]);
        p[1] = make_float4(o[4], o[5], o[6], o[7]);
    }
}

// ---------------- agg width 64: warp/node, scalar loads, 4-edge unroll -------
// h is pre-scaled by dinv[src]. result = dinv[dst]*(sum gathered + self).
template <bool POOL>
__global__ void k_agg64(const float* __restrict__ h,
                        const int* __restrict__ rowptr, const int* __restrict__ col,
                        const float* __restrict__ dinv,
                        const float* __restrict__ bias,
                        const void* __restrict__ batch, const int* flag,
                        float* __restrict__ out, float* pool, float* gcnt, int n) {
    int node = blockIdx.x * 8 + (threadIdx.x >> 5);
    int lane = threadIdx.x & 31;
    if (node >= n) return;
    int beg = rowptr[node], end = rowptr[node + 1];
    float a0 = 0.f, a1 = 0.f;
    int e = beg;
    for (; e + 3 < end; e += 4) {
        int s0 = col[e], s1 = col[e + 1], s2 = col[e + 2], s3 = col[e + 3];
        const float* p0 = h + (size_t)s0 * 64;
        const float* p1 = h + (size_t)s1 * 64;
        const float* p2 = h + (size_t)s2 * 64;
        const float* p3 = h + (size_t)s3 * 64;
        float x00 = __ldg(p0 + lane),      x01 = __ldg(p0 + lane + 32);
        float x10 = __ldg(p1 + lane),      x11 = __ldg(p1 + lane + 32);
        float x20 = __ldg(p2 + lane),      x21 = __ldg(p2 + lane + 32);
        float x30 = __ldg(p3 + lane),      x31 = __ldg(p3 + lane + 32);
        a0 += (x00 + x10) + (x20 + x30);
        a1 += (x01 + x11) + (x21 + x31);
    }
    for (; e < end; e++) {
        int s = col[e];
        a0 += __ldg(&h[(size_t)s * 64 + lane]);
        a1 += __ldg(&h[(size_t)s * 64 + lane + 32]);
    }
    float ds = dinv[node];
    a0 = ds * (a0 + h[(size_t)node * 64 + lane]);
    a1 = ds * (a1 + h[(size_t)node * 64 + lane + 32]);
    if (POOL) {
        a0 = fmaxf(a0 + __ldg(&bias[lane]), 0.f);
        a1 = fmaxf(a1 + __ldg(&bias[lane + 32]), 0.f);
        int g = load_idx(batch, node, flag[0]);
        atomicAdd(&pool[g * 64 + lane], a0);
        atomicAdd(&pool[g * 64 + lane + 32], a1);
        if (lane == 0) atomicAdd(&gcnt[g], 1.0f);
    } else {
        out[(size_t)node * 64 + lane]      = a0;
        out[(size_t)node * 64 + lane + 32] = a1;
    }
}

// ---------------- tiled fp32 GEMM: 64-node tile x NC cols ----------------
// SCALE: multiply output row by dinv[node] (prescale for next aggregation)
template <int K, int NC, int MC, bool RELU, bool SCALE>
__launch_bounds__(256)
__global__ void k_gemm(const float* __restrict__ A, const float* __restrict__ W,
                       const float* __restrict__ bias, const float* __restrict__ dinv,
                       float* __restrict__ out, int n) {
    constexpr int KC = 64;
    __shared__ float As[KC][64];
    __shared__ float Bs[KC][NC];
    const int t = threadIdx.x;
    const int tx = t & 15;
    const int ty = t >> 4;
    const int nodeBase = blockIdx.x * 64;

    float acc[4][MC];
#pragma unroll
    for (int i = 0; i < 4; i++)
#pragma unroll
        for (int j = 0; j < MC; j++) acc[i][j] = 0.f;

    for (int k0 = 0; k0 < K; k0 += KC) {
        for (int q = t; q < 64 * KC / 4; q += 256) {
            int node = q >> 4;
            int kk4 = (q & 15) * 4;
            int gn = nodeBase + node;
            float4 v = make_float4(0.f, 0.f, 0.f, 0.f);
            if (gn < n)
                v = *reinterpret_cast<const float4*>(&A[(size_t)gn * K + k0 + kk4]);
            As[kk4 + 0][node] = v.x;
            As[kk4 + 1][node] = v.y;
            As[kk4 + 2][node] = v.z;
            As[kk4 + 3][node] = v.w;
        }
        for (int q = t; q < KC * NC / 4; q += 256) {
            int kk = q / (NC / 4);
            int c4 = (q % (NC / 4)) * 4;
            *reinterpret_cast<float4*>(&Bs[kk][c4]) =
                *reinterpret_cast<const float4*>(&W[(size_t)(k0 + kk) * NC + c4]);
        }
        __syncthreads();
#pragma unroll
        for (int kk = 0; kk < KC; kk++) {
            float4 av = *reinterpret_cast<const float4*>(&As[kk][ty * 4]);
            float a4[4] = {av.x, av.y, av.z, av.w};
            float bv[MC];
#pragma unroll
            for (int j = 0; j < MC; j += 4) {
                float4 b4 = *reinterpret_cast<const float4*>(&Bs[kk][tx * MC + j]);
                bv[j] = b4.x; bv[j + 1] = b4.y; bv[j + 2] = b4.z; bv[j + 3] = b4.w;
            }
#pragma unroll
            for (int i = 0; i < 4; i++)
#pragma unroll
                for (int j = 0; j < MC; j++) acc[i][j] += a4[i] * bv[j];
        }
        __syncthreads();
    }
#pragma unroll
    for (int i = 0; i < 4; i++) {
        int gn = nodeBase + ty * 4 + i;
        if (gn < n) {
            float ds = SCALE ? dinv[gn] : 1.0f;
#pragma unroll
            for (int j = 0; j < MC; j++) {
                int c = tx * MC + j;
                float v = acc[i][j];
                if (RELU) v = fmaxf(v + __ldg(&bias[c]), 0.f);
                if (SCALE) v *= ds;
                out[(size_t)gn * NC + c] = v;
            }
        }
    }
}

// ---------------- final FC + sigmoid ----------------
__global__ void k_final(const float* __restrict__ pool, const float* __restrict__ gcnt,
                        const float* __restrict__ Wfc, const float* __restrict__ bfc,
                        float* __restrict__ out) {
    int g = threadIdx.x;
    float c = fmaxf(gcnt[g], 1.0f);
    float acc = 0.f;
#pragma unroll
    for (int k = 0; k < 64; k++) acc += pool[g * 64 + k] * Wfc[k];
    acc = acc / c + bfc[0];
    out[g] = 1.f / (1.f + expf(-acc));
}

// ---------------- launch ----------------
extern "C" void kernel_launch(void* const* d_in, const int* in_sizes, int n_in,
                              void* d_out, int out_size) {
    const float*  x     = (const float*)d_in[0];
    const void*   ei    = d_in[1];
    const void*   batch = d_in[2];
    const float*  W1    = (const float*)d_in[3];
    const float*  b1    = (const float*)d_in[4];
    const float*  W2    = (const float*)d_in[5];
    const float*  b2    = (const float*)d_in[6];
    const float*  W3    = (const float*)d_in[7];
    const float*  b3    = (const float*)d_in[8];
    const float*  Wfc   = (const float*)d_in[9];
    const float*  bfc   = (const float*)d_in[10];
    float*        out   = (float*)d_out;

    const int N = in_sizes[0] / 5;
    const int E = in_sizes[1] / 2;

    float *bufA, *bufB, *xs, *dinv, *pool, *gcnt;
    int *cnt, *rowptr, *curoff, *col, *bsums, *is64;
    cudaGetSymbolAddress((void**)&bufA, g_bufA);
    cudaGetSymbolAddress((void**)&bufB, g_bufB);
    cudaGetSymbolAddress((void**)&xs, g_xs);
    cudaGetSymbolAddress((void**)&dinv, g_dinv);
    cudaGetSymbolAddress((void**)&pool, g_pool);
    cudaGetSymbolAddress((void**)&gcnt, g_gcnt);
    cudaGetSymbolAddress((void**)&cnt, g_cnt);
    cudaGetSymbolAddress((void**)&rowptr, g_rowptr);
    cudaGetSymbolAddress((void**)&curoff, g_curoff);
    cudaGetSymbolAddress((void**)&col, g_col);
    cudaGetSymbolAddress((void**)&bsums, g_bsums);
    cudaGetSymbolAddress((void**)&is64, g_is64);

    const int TB = 256;
    int initN = N > NGRAPH * 64 ? N : NGRAPH * 64;
    k_init<<<(initN + TB - 1) / TB, TB>>>(cnt, pool, gcnt, N, (const int*)ei, is64);
    k_count<<<(E + TB - 1) / TB, TB>>>(ei, E, cnt, is64);

    int nb = (N + 1023) / 1024;
    k_scan1<<<nb, 1024>>>(cnt, rowptr, bsums, N);
    k_scan2<<<1, 128>>>(bsums, nb);
    k_scan3<<<(N + TB - 1) / TB, TB>>>(rowptr, curoff, bsums, cnt, dinv, x, xs, N, E);
    k_fill<<<(E + TB - 1) / TB, TB>>>(ei, E, curoff, col, is64);

    // L1 fused: agg5 + GEMM(5->64) + relu, output prescaled by dinv -> bufA
    k_l1<<<(N * 8 + TB - 1) / TB, TB>>>(xs, rowptr, col, dinv, W1, b1, bufA, N);

    // L2: agg (pure adds) -> bufB; GEMM(64->128)+b2+relu -> bufA
    k_agg64<false><<<(N + 7) / 8, TB>>>(bufA, rowptr, col, dinv, nullptr,
                                        nullptr, is64, bufB, nullptr, nullptr, N);
    k_gemm<64, 128, 8, true, false><<<(N + 63) / 64, TB>>>(bufB, W2, b2, nullptr, bufA, N);

    // L3: GEMM(128->64), epilogue *dinv -> bufB; agg + b3 + relu + pool (fused)
    k_gemm<128, 64, 4, false, true><<<(N + 63) / 64, TB>>>(bufA, W3, nullptr, dinv, bufB, N);
    k_agg64<true><<<(N + 7) / 8, TB>>>(bufB, rowptr, col, dinv, b3,
                                       batch, is64, nullptr, pool, gcnt, N);

    k_final<<<1, NGRAPH>>>(pool, gcnt, Wfc, bfc, out);
}

// round 8
// speedup vs baseline: 1.4220x; 1.2662x over previous
#include <cuda_runtime.h>
#include <cuda_bf16.h>
#include <math.h>
#include <stdint.h>

// ---------------- static scratch (no allocations allowed) ----------------
#define MAXN 100000
#define MAXE 1600000
#define NGRAPH 256

__device__ float g_bufA[(size_t)MAXN * 128];
__device__ float g_bufB[(size_t)MAXN * 64];
__device__ float g_xs[(size_t)MAXN * 5];
__device__ int   g_cnt[MAXN];
__device__ int   g_rowptr[MAXN + 1];
__device__ int   g_curoff[MAXN];
__device__ float g_dinv[MAXN];
__device__ int   g_col[MAXE];
__device__ int   g_bsums[128];
__device__ float g_pool[NGRAPH * 64];
__device__ float g_gcnt[NGRAPH];
__device__ int   g_is64[1];

__device__ __forceinline__ int load_idx(const void* p, long long i, int is64) {
    if (is64) return (int)((const long long*)p)[i];
    return ((const int*)p)[i];
}

// split a pair of floats into packed bf16 hi and lo words (low half = first elem)
__device__ __forceinline__ void split2(float a, float b, uint32_t& hi, uint32_t& lo) {
    __nv_bfloat16 ah = __float2bfloat16(a);
    __nv_bfloat16 bh = __float2bfloat16(b);
    __nv_bfloat16 al = __float2bfloat16(a - __bfloat162float(ah));
    __nv_bfloat16 bl = __float2bfloat16(b - __bfloat162float(bh));
    unsigned short ahu = *(unsigned short*)&ah, bhu = *(unsigned short*)&bh;
    unsigned short alu = *(unsigned short*)&al, blu = *(unsigned short*)&bl;
    hi = ((uint32_t)bhu << 16) | ahu;
    lo = ((uint32_t)blu << 16) | alu;
}

__device__ __forceinline__ void mma16816(float* d, const uint32_t* a,
                                         uint32_t b0, uint32_t b1) {
    asm volatile(
        "mma.sync.aligned.m16n8k16.row.col.f32.bf16.bf16.f32 "
        "{%0,%1,%2,%3}, {%4,%5,%6,%7}, {%8,%9}, {%0,%1,%2,%3};"
        : "+f"(d[0]), "+f"(d[1]), "+f"(d[2]), "+f"(d[3])
        : "r"(a[0]), "r"(a[1]), "r"(a[2]), "r"(a[3]), "r"(b0), "r"(b1));
}

// ---------------- init (+ dtype detect in block 0) ----------------
__global__ void k_init(int* cnt, float* pool, float* gcnt, int n,
                       const int* __restrict__ eprobe, int* flag) {
    int i = blockIdx.x * blockDim.x + threadIdx.x;
    if (i < n) cnt[i] = 0;
    if (i < NGRAPH * 64) pool[i] = 0.f;
    if (i < NGRAPH) gcnt[i] = 0.f;
    if (blockIdx.x == 0) {
        __shared__ int any;
        if (threadIdx.x == 0) any = 0;
        __syncthreads();
        int loc = 0;
        for (int q = threadIdx.x; q < 512; q += blockDim.x)
            if (eprobe[2 * q + 1] != 0) loc = 1;
        if (loc) atomicOr(&any, 1);
        __syncthreads();
        if (threadIdx.x == 0) flag[0] = any ? 0 : 1;
    }
}

__global__ void k_count(const void* __restrict__ ei, int E, int* cnt, const int* flag) {
    int is64 = flag[0];
    int e = blockIdx.x * blockDim.x + threadIdx.x;
    if (e < E) {
        int d = load_idx(ei, (long long)E + e, is64);
        atomicAdd(&cnt[d], 1);
    }
}

__global__ void k_scan1(const int* __restrict__ cnt, int* rowptr, int* bsums, int n) {
    __shared__ int s[1024];
    int i = blockIdx.x * 1024 + threadIdx.x;
    int v = (i < n) ? cnt[i] : 0;
    s[threadIdx.x] = v;
    __syncthreads();
    for (int off = 1; off < 1024; off <<= 1) {
        int t = 0;
        if ((int)threadIdx.x >= off) t = s[threadIdx.x - off];
        __syncthreads();
        s[threadIdx.x] += t;
        __syncthreads();
    }
    if (i < n) rowptr[i] = s[threadIdx.x] - v;
    if (threadIdx.x == 1023) bsums[blockIdx.x] = s[1023];
}

__global__ void k_scan2(int* bsums, int nb) {
    int t = threadIdx.x;
    int v = (t < nb) ? bsums[t] : 0;
    int orig = v;
#pragma unroll
    for (int off = 1; off < 32; off <<= 1) {
        int u = __shfl_up_sync(0xffffffffu, v, off);
        if ((t & 31) >= off) v += u;
    }
    __shared__ int ws[4];
    if ((t & 31) == 31) ws[t >> 5] = v;
    __syncthreads();
    if (t == 0) { int a = 0; for (int i = 0; i < 4; i++) { int x = ws[i]; ws[i] = a; a += x; } }
    __syncthreads();
    v += ws[t >> 5];
    if (t < nb) bsums[t] = v - orig;
}

__global__ void k_scan3(int* rowptr, int* curoff, const int* __restrict__ bsums,
                        const int* __restrict__ cnt, float* dinv,
                        const float* __restrict__ x, float* xs, int n, int E) {
    int i = blockIdx.x * blockDim.x + threadIdx.x;
    if (i < n) {
        int r = rowptr[i] + bsums[i >> 10];
        rowptr[i] = r;
        curoff[i] = r;
        float d = rsqrtf((float)cnt[i] + 1.0f);
        dinv[i] = d;
#pragma unroll
        for (int k = 0; k < 5; k++) xs[(size_t)i * 5 + k] = d * x[(size_t)i * 5 + k];
    }
    if (i == 0) rowptr[n] = E;
}

__global__ void k_fill(const void* __restrict__ ei, int E,
                       int* curoff, int* col, const int* flag) {
    int is64 = flag[0];
    int e = blockIdx.x * blockDim.x + threadIdx.x;
    if (e >= E) return;
    int s = load_idx(ei, e, is64);
    int d = load_idx(ei, (long long)E + e, is64);
    int p = atomicAdd(&curoff[d], 1);
    col[p] = s;
}

// ---------------- fused layer1: agg(xs) + GEMM(5->64) + relu + prescale ------
__global__ void k_l1(const float* __restrict__ xs,
                     const int* __restrict__ rowptr, const int* __restrict__ col,
                     const float* __restrict__ dinv,
                     const float* __restrict__ W1, const float* __restrict__ b1,
                     float* __restrict__ out, int n) {
    __shared__ float Ws[5 * 64];
    __shared__ float bs[64];
    int t = threadIdx.x;
    for (int i = t; i < 5 * 64; i += 256) Ws[i] = W1[i];
    if (t < 64) bs[t] = b1[t];
    __syncthreads();

    int gt = blockIdx.x * 256 + t;
    int node = gt >> 3;
    int f = gt & 7;
    bool live = (node < n);
    int nodec = live ? node : (n - 1);

    int beg = rowptr[nodec], end = rowptr[nodec + 1];
    bool valid = (f < 5);
    float acc = 0.f;
    for (int e = beg; e < end; e++) {
        int s = col[e];
        if (valid) acc += __ldg(&xs[(size_t)s * 5 + f]);
    }
    float ds = dinv[nodec];
    if (valid) acc = ds * (acc + xs[(size_t)nodec * 5 + f]);

    float v[5];
#pragma unroll
    for (int k = 0; k < 5; k++) v[k] = __shfl_sync(0xffffffffu, acc, k, 8);

    int cb = f * 8;
    float o[8];
#pragma unroll
    for (int j = 0; j < 8; j++) {
        float a = bs[cb + j];
#pragma unroll
        for (int k = 0; k < 5; k++) a += v[k] * Ws[k * 64 + cb + j];
        o[j] = fmaxf(a, 0.f) * ds;
    }
    if (live) {
        float4* p = reinterpret_cast<float4*>(&out[(size_t)node * 64 + cb]);
        p[0] = make_float4(o[0], o[1], o[2], o[3]);
        p[1] = make_float4(o[4], o[5], o[6], o[7]);
    }
}

// ---------------- agg width 64: warp/node, scalar loads, 4-edge unroll -------
template <bool POOL>
__global__ void k_agg64(const float* __restrict__ h,
                        const int* __restrict__ rowptr, const int* __restrict__ col,
                        const float* __restrict__ dinv,
                        const float* __restrict__ bias,
                        const void* __restrict__ batch, const int* flag,
                        float* __restrict__ out, float* pool, float* gcnt, int n) {
    int node = blockIdx.x * 8 + (threadIdx.x >> 5);
    int lane = threadIdx.x & 31;
    if (node >= n) return;
    int beg = rowptr[node], end = rowptr[node + 1];
    float a0 = 0.f, a1 = 0.f;
    int e = beg;
    for (; e + 3 < end; e += 4) {
        int s0 = col[e], s1 = col[e + 1], s2 = col[e + 2], s3 = col[e + 3];
        const float* p0 = h + (size_t)s0 * 64;
        const float* p1 = h + (size_t)s1 * 64;
        const float* p2 = h + (size_t)s2 * 64;
        const float* p3 = h + (size_t)s3 * 64;
        float x00 = __ldg(p0 + lane),      x01 = __ldg(p0 + lane + 32);
        float x10 = __ldg(p1 + lane),      x11 = __ldg(p1 + lane + 32);
        float x20 = __ldg(p2 + lane),      x21 = __ldg(p2 + lane + 32);
        float x30 = __ldg(p3 + lane),      x31 = __ldg(p3 + lane + 32);
        a0 += (x00 + x10) + (x20 + x30);
        a1 += (x01 + x11) + (x21 + x31);
    }
    for (; e < end; e++) {
        int s = col[e];
        a0 += __ldg(&h[(size_t)s * 64 + lane]);
        a1 += __ldg(&h[(size_t)s * 64 + lane + 32]);
    }
    float ds = dinv[node];
    a0 = ds * (a0 + h[(size_t)node * 64 + lane]);
    a1 = ds * (a1 + h[(size_t)node * 64 + lane + 32]);
    if (POOL) {
        a0 = fmaxf(a0 + __ldg(&bias[lane]), 0.f);
        a1 = fmaxf(a1 + __ldg(&bias[lane + 32]), 0.f);
        int g = load_idx(batch, node, flag[0]);
        atomicAdd(&pool[g * 64 + lane], a0);
        atomicAdd(&pool[g * 64 + lane + 32], a1);
        if (lane == 0) atomicAdd(&gcnt[g], 1.0f);
    } else {
        out[(size_t)node * 64 + lane]      = a0;
        out[(size_t)node * 64 + lane + 32] = a1;
    }
}

// ---------------- mma.sync bf16 split GEMM: 128-row tile, 8 warps ----------
// D[128,NC] = A[128,K] @ W[K,NC]; 3-term bf16 hi/lo split, fp32 accum.
// Warp w computes rows [16w,16w+16). Fragments loaded as plain uint32 from
// padded row-major smem (pitch P = K+8 bf16) — conflict-free, no ldmatrix.
template <int K, int NC, bool RELU, bool SCALE>
__launch_bounds__(256)
__global__ void k_gemm_mma(const float* __restrict__ A, const float* __restrict__ W,
                           const float* __restrict__ bias, const float* __restrict__ dinv,
                           float* __restrict__ out, int n) {
    constexpr int P = K + 8;
    extern __shared__ char sm[];
    uint16_t* Ah = (uint16_t*)sm;              // [128][P]
    uint16_t* Al = Ah + 128 * P;
    uint16_t* Bh = Al + 128 * P;               // [NC][P]
    uint16_t* Bl = Bh + NC * P;

    const int tid = threadIdx.x;
    const int nodeBase = blockIdx.x * 128;

    // convert A tile -> bf16 hi/lo
    for (int q = tid; q < 128 * (K / 2); q += 256) {
        int r = q / (K / 2);
        int c2 = (q % (K / 2)) * 2;
        int gn = nodeBase + r;
        float2 v = (gn < n) ? *reinterpret_cast<const float2*>(&A[(size_t)gn * K + c2])
                            : make_float2(0.f, 0.f);
        uint32_t h, l;
        split2(v.x, v.y, h, l);
        *(uint32_t*)&Ah[r * P + c2] = h;
        *(uint32_t*)&Al[r * P + c2] = l;
    }
    // convert W -> Bsm[n][k] bf16 hi/lo (coalesced reads of W rows)
    for (int q = tid; q < NC * (K / 2); q += 256) {
        int nrow = q % NC;
        int k2 = (q / NC) * 2;
        float a = __ldg(&W[(size_t)k2 * NC + nrow]);
        float b = __ldg(&W[(size_t)(k2 + 1) * NC + nrow]);
        uint32_t h, l;
        split2(a, b, h, l);
        *(uint32_t*)&Bh[nrow * P + k2] = h;
        *(uint32_t*)&Bl[nrow * P + k2] = l;
    }
    __syncthreads();

    const int wid = tid >> 5;
    const int lane = tid & 31;
    const int g = lane >> 2;
    const int t4 = lane & 3;
    const int warpRow = wid * 16;

    float acc[NC / 8][4];
#pragma unroll
    for (int nt = 0; nt < NC / 8; nt++)
#pragma unroll
        for (int j = 0; j < 4; j++) acc[nt][j] = 0.f;

#pragma unroll
    for (int ks = 0; ks < K / 16; ks++) {
        int k0 = ks * 16;
        int r0 = warpRow + g;
        uint32_t ah[4], al[4];
        ah[0] = *(uint32_t*)&Ah[r0 * P + k0 + 2 * t4];
        ah[1] = *(uint32_t*)&Ah[(r0 + 8) * P + k0 + 2 * t4];
        ah[2] = *(uint32_t*)&Ah[r0 * P + k0 + 2 * t4 + 8];
        ah[3] = *(uint32_t*)&Ah[(r0 + 8) * P + k0 + 2 * t4 + 8];
        al[0] = *(uint32_t*)&Al[r0 * P + k0 + 2 * t4];
        al[1] = *(uint32_t*)&Al[(r0 + 8) * P + k0 + 2 * t4];
        al[2] = *(uint32_t*)&Al[r0 * P + k0 + 2 * t4 + 8];
        al[3] = *(uint32_t*)&Al[(r0 + 8) * P + k0 + 2 * t4 + 8];
#pragma unroll
        for (int nt = 0; nt < NC / 8; nt++) {
            int nr = nt * 8 + g;
            uint32_t bh0 = *(uint32_t*)&Bh[nr * P + k0 + 2 * t4];
            uint32_t bh1 = *(uint32_t*)&Bh[nr * P + k0 + 2 * t4 + 8];
            uint32_t bl0 = *(uint32_t*)&Bl[nr * P + k0 + 2 * t4];
            uint32_t bl1 = *(uint32_t*)&Bl[nr * P + k0 + 2 * t4 + 8];
            mma16816(acc[nt], ah, bh0, bh1);
            mma16816(acc[nt], ah, bl0, bl1);
            mma16816(acc[nt], al, bh0, bh1);
        }
    }

    // epilogue: c0=C[g][2t], c1=C[g][2t+1], c2=C[g+8][2t], c3=C[g+8][2t+1]
    int row0 = nodeBase + warpRow + g;
    int row1 = row0 + 8;
    bool l0 = row0 < n, l1 = row1 < n;
    float ds0 = (SCALE && l0) ? dinv[row0] : 1.0f;
    float ds1 = (SCALE && l1) ? dinv[row1] : 1.0f;
#pragma unroll
    for (int nt = 0; nt < NC / 8; nt++) {
        int col = nt * 8 + 2 * t4;
        float b0 = RELU ? __ldg(&bias[col]) : 0.f;
        float b1 = RELU ? __ldg(&bias[col + 1]) : 0.f;
        float v0 = acc[nt][0], v1 = acc[nt][1], v2 = acc[nt][2], v3 = acc[nt][3];
        if (RELU) {
            v0 = fmaxf(v0 + b0, 0.f); v1 = fmaxf(v1 + b1, 0.f);
            v2 = fmaxf(v2 + b0, 0.f); v3 = fmaxf(v3 + b1, 0.f);
        }
        if (SCALE) { v0 *= ds0; v1 *= ds0; v2 *= ds1; v3 *= ds1; }
        if (l0) *reinterpret_cast<float2*>(&out[(size_t)row0 * NC + col]) = make_float2(v0, v1);
        if (l1) *reinterpret_cast<float2*>(&out[(size_t)row1 * NC + col]) = make_float2(v2, v3);
    }
}

// ---------------- final FC + sigmoid ----------------
__global__ void k_final(const float* __restrict__ pool, const float* __restrict__ gcnt,
                        const float* __restrict__ Wfc, const float* __restrict__ bfc,
                        float* __restrict__ out) {
    int g = threadIdx.x;
    float c = fmaxf(gcnt[g], 1.0f);
    float acc = 0.f;
#pragma unroll
    for (int k = 0; k < 64; k++) acc += pool[g * 64 + k] * Wfc[k];
    acc = acc / c + bfc[0];
    out[g] = 1.f / (1.f + expf(-acc));
}

// ---------------- launch ----------------
extern "C" void kernel_launch(void* const* d_in, const int* in_sizes, int n_in,
                              void* d_out, int out_size) {
    const float*  x     = (const float*)d_in[0];
    const void*   ei    = d_in[1];
    const void*   batch = d_in[2];
    const float*  W1    = (const float*)d_in[3];
    const float*  b1    = (const float*)d_in[4];
    const float*  W2    = (const float*)d_in[5];
    const float*  b2    = (const float*)d_in[6];
    const float*  W3    = (const float*)d_in[7];
    const float*  b3    = (const float*)d_in[8];
    const float*  Wfc   = (const float*)d_in[9];
    const float*  bfc   = (const float*)d_in[10];
    float*        out   = (float*)d_out;

    const int N = in_sizes[0] / 5;
    const int E = in_sizes[1] / 2;

    float *bufA, *bufB, *xs, *dinv, *pool, *gcnt;
    int *cnt, *rowptr, *curoff, *col, *bsums, *is64;
    cudaGetSymbolAddress((void**)&bufA, g_bufA);
    cudaGetSymbolAddress((void**)&bufB, g_bufB);
    cudaGetSymbolAddress((void**)&xs, g_xs);
    cudaGetSymbolAddress((void**)&dinv, g_dinv);
    cudaGetSymbolAddress((void**)&pool, g_pool);
    cudaGetSymbolAddress((void**)&gcnt, g_gcnt);
    cudaGetSymbolAddress((void**)&cnt, g_cnt);
    cudaGetSymbolAddress((void**)&rowptr, g_rowptr);
    cudaGetSymbolAddress((void**)&curoff, g_curoff);
    cudaGetSymbolAddress((void**)&col, g_col);
    cudaGetSymbolAddress((void**)&bsums, g_bsums);
    cudaGetSymbolAddress((void**)&is64, g_is64);

    // smem: gemm2 (K=64,P=72): (128+128)*72*2*2 = 73728 B
    //       gemm3 (K=128,P=136): (128*136 + 64*136)*2*2 = 104448 B
    const int SM2 = (128 + 128) * (64 + 8) * 2 * 2;
    const int SM3 = (128 + 64) * (128 + 8) * 2 * 2;
    static int smem_set = 0;
    if (!smem_set) {
        cudaFuncSetAttribute(k_gemm_mma<64, 128, true, false>,
                             cudaFuncAttributeMaxDynamicSharedMemorySize, SM2);
        cudaFuncSetAttribute(k_gemm_mma<128, 64, false, true>,
                             cudaFuncAttributeMaxDynamicSharedMemorySize, SM3);
        smem_set = 1;
    }

    const int TB = 256;
    int initN = N > NGRAPH * 64 ? N : NGRAPH * 64;
    k_init<<<(initN + TB - 1) / TB, TB>>>(cnt, pool, gcnt, N, (const int*)ei, is64);
    k_count<<<(E + TB - 1) / TB, TB>>>(ei, E, cnt, is64);

    int nb = (N + 1023) / 1024;
    k_scan1<<<nb, 1024>>>(cnt, rowptr, bsums, N);
    k_scan2<<<1, 128>>>(bsums, nb);
    k_scan3<<<(N + TB - 1) / TB, TB>>>(rowptr, curoff, bsums, cnt, dinv, x, xs, N, E);
    k_fill<<<(E + TB - 1) / TB, TB>>>(ei, E, curoff, col, is64);

    // L1 fused: agg5 + GEMM(5->64) + relu, prescaled by dinv -> bufA
    k_l1<<<(N * 8 + TB - 1) / TB, TB>>>(xs, rowptr, col, dinv, W1, b1, bufA, N);

    // L2: agg -> bufB; mma GEMM(64->128)+b2+relu -> bufA
    k_agg64<false><<<(N + 7) / 8, TB>>>(bufA, rowptr, col, dinv, nullptr,
                                        nullptr, is64, bufB, nullptr, nullptr, N);
    int gtc = (N + 127) / 128;
    k_gemm_mma<64, 128, true, false><<<gtc, 256, SM2>>>(bufB, W2, b2, nullptr, bufA, N);

    // L3: mma GEMM(128->64) *dinv -> bufB; agg + b3 + relu + pool (fused)
    k_gemm_mma<128, 64, false, true><<<gtc, 256, SM3>>>(bufA, W3, nullptr, dinv, bufB, N);
    k_agg64<true><<<(N + 7) / 8, TB>>>(bufB, rowptr, col, dinv, b3,
                                       batch, is64, nullptr, pool, gcnt, N);

    k_final<<<1, NGRAPH>>>(pool, gcnt, Wfc, bfc, out);
}

// round 9
// speedup vs baseline: 1.4334x; 1.0080x over previous
#include <cuda_runtime.h>
#include <cuda_bf16.h>
#include <cuda_fp16.h>
#include <math.h>
#include <stdint.h>

// ---------------- static scratch (no allocations allowed) ----------------
#define MAXN 100000
#define MAXE 1600000
#define NGRAPH 256

__device__ float  g_bufA[(size_t)MAXN * 128];   // fp32 ping (N x 128)
__device__ float  g_bufB[(size_t)MAXN * 64];    // fp32 pong (N x 64)
__device__ __half g_h1[(size_t)MAXN * 64];      // fp16 gather array (layer1 out)
__device__ __half g_h3[(size_t)MAXN * 64];      // fp16 gather array (gemm3 out)
__device__ float  g_xs[(size_t)MAXN * 5];
__device__ int    g_cnt[MAXN];
__device__ int    g_rowptr[MAXN + 1];
__device__ int    g_curoff[MAXN];
__device__ float  g_dinv[MAXN];
__device__ int    g_col[MAXE];
__device__ int    g_bsums[128];
__device__ float  g_pool[NGRAPH * 64];
__device__ float  g_gcnt[NGRAPH];
__device__ int    g_is64[1];

__device__ __forceinline__ int load_idx(const void* p, long long i, int is64) {
    if (is64) return (int)((const long long*)p)[i];
    return ((const int*)p)[i];
}

// split a pair of floats into packed bf16 hi and lo words
__device__ __forceinline__ void split2(float a, float b, uint32_t& hi, uint32_t& lo) {
    __nv_bfloat16 ah = __float2bfloat16(a);
    __nv_bfloat16 bh = __float2bfloat16(b);
    __nv_bfloat16 al = __float2bfloat16(a - __bfloat162float(ah));
    __nv_bfloat16 bl = __float2bfloat16(b - __bfloat162float(bh));
    unsigned short ahu = *(unsigned short*)&ah, bhu = *(unsigned short*)&bh;
    unsigned short alu = *(unsigned short*)&al, blu = *(unsigned short*)&bl;
    hi = ((uint32_t)bhu << 16) | ahu;
    lo = ((uint32_t)blu << 16) | alu;
}

__device__ __forceinline__ void mma16816(float* d, const uint32_t* a,
                                         uint32_t b0, uint32_t b1) {
    asm volatile(
        "mma.sync.aligned.m16n8k16.row.col.f32.bf16.bf16.f32 "
        "{%0,%1,%2,%3}, {%4,%5,%6,%7}, {%8,%9}, {%0,%1,%2,%3};"
        : "+f"(d[0]), "+f"(d[1]), "+f"(d[2]), "+f"(d[3])
        : "r"(a[0]), "r"(a[1]), "r"(a[2]), "r"(a[3]), "r"(b0), "r"(b1));
}

// ---------------- init (+ dtype detect in block 0) ----------------
__global__ void k_init(int* cnt, float* pool, float* gcnt, int n,
                       const int* __restrict__ eprobe, int* flag) {
    int i = blockIdx.x * blockDim.x + threadIdx.x;
    if (i < n) cnt[i] = 0;
    if (i < NGRAPH * 64) pool[i] = 0.f;
    if (i < NGRAPH) gcnt[i] = 0.f;
    if (blockIdx.x == 0) {
        __shared__ int any;
        if (threadIdx.x == 0) any = 0;
        __syncthreads();
        int loc = 0;
        for (int q = threadIdx.x; q < 512; q += blockDim.x)
            if (eprobe[2 * q + 1] != 0) loc = 1;
        if (loc) atomicOr(&any, 1);
        __syncthreads();
        if (threadIdx.x == 0) flag[0] = any ? 0 : 1;
    }
}

__global__ void k_count(const void* __restrict__ ei, int E, int* cnt, const int* flag) {
    int is64 = flag[0];
    int e = blockIdx.x * blockDim.x + threadIdx.x;
    if (e < E) {
        int d = load_idx(ei, (long long)E + e, is64);
        atomicAdd(&cnt[d], 1);
    }
}

__global__ void k_scan1(const int* __restrict__ cnt, int* rowptr, int* bsums, int n) {
    __shared__ int s[1024];
    int i = blockIdx.x * 1024 + threadIdx.x;
    int v = (i < n) ? cnt[i] : 0;
    s[threadIdx.x] = v;
    __syncthreads();
    for (int off = 1; off < 1024; off <<= 1) {
        int t = 0;
        if ((int)threadIdx.x >= off) t = s[threadIdx.x - off];
        __syncthreads();
        s[threadIdx.x] += t;
        __syncthreads();
    }
    if (i < n) rowptr[i] = s[threadIdx.x] - v;
    if (threadIdx.x == 1023) bsums[blockIdx.x] = s[1023];
}

__global__ void k_scan2(int* bsums, int nb) {
    int t = threadIdx.x;
    int v = (t < nb) ? bsums[t] : 0;
    int orig = v;
#pragma unroll
    for (int off = 1; off < 32; off <<= 1) {
        int u = __shfl_up_sync(0xffffffffu, v, off);
        if ((t & 31) >= off) v += u;
    }
    __shared__ int ws[4];
    if ((t & 31) == 31) ws[t >> 5] = v;
    __syncthreads();
    if (t == 0) { int a = 0; for (int i = 0; i < 4; i++) { int x = ws[i]; ws[i] = a; a += x; } }
    __syncthreads();
    v += ws[t >> 5];
    if (t < nb) bsums[t] = v - orig;
}

__global__ void k_scan3(int* rowptr, int* curoff, const int* __restrict__ bsums,
                        const int* __restrict__ cnt, float* dinv,
                        const float* __restrict__ x, float* xs, int n, int E) {
    int i = blockIdx.x * blockDim.x + threadIdx.x;
    if (i < n) {
        int r = rowptr[i] + bsums[i >> 10];
        rowptr[i] = r;
        curoff[i] = r;
        float d = rsqrtf((float)cnt[i] + 1.0f);
        dinv[i] = d;
#pragma unroll
        for (int k = 0; k < 5; k++) xs[(size_t)i * 5 + k] = d * x[(size_t)i * 5 + k];
    }
    if (i == 0) rowptr[n] = E;
}

__global__ void k_fill(const void* __restrict__ ei, int E,
                       int* curoff, int* col, const int* flag) {
    int is64 = flag[0];
    int e = blockIdx.x * blockDim.x + threadIdx.x;
    if (e >= E) return;
    int s = load_idx(ei, e, is64);
    int d = load_idx(ei, (long long)E + e, is64);
    int p = atomicAdd(&curoff[d], 1);
    col[p] = s;
}

// ---------------- fused layer1: agg(xs) + GEMM(5->64) + relu + prescale ------
// output: fp16 (gather array for layer-2 aggregation)
__global__ void k_l1(const float* __restrict__ xs,
                     const int* __restrict__ rowptr, const int* __restrict__ col,
                     const float* __restrict__ dinv,
                     const float* __restrict__ W1, const float* __restrict__ b1,
                     __half* __restrict__ out, int n) {
    __shared__ float Ws[5 * 64];
    __shared__ float bs[64];
    int t = threadIdx.x;
    for (int i = t; i < 5 * 64; i += 256) Ws[i] = W1[i];
    if (t < 64) bs[t] = b1[t];
    __syncthreads();

    int gt = blockIdx.x * 256 + t;
    int node = gt >> 3;
    int f = gt & 7;
    bool live = (node < n);
    int nodec = live ? node : (n - 1);

    int beg = rowptr[nodec], end = rowptr[nodec + 1];
    bool valid = (f < 5);
    float acc = 0.f;
    for (int e = beg; e < end; e++) {
        int s = col[e];
        if (valid) acc += __ldg(&xs[(size_t)s * 5 + f]);
    }
    float ds = dinv[nodec];
    if (valid) acc = ds * (acc + xs[(size_t)nodec * 5 + f]);

    float v[5];
#pragma unroll
    for (int k = 0; k < 5; k++) v[k] = __shfl_sync(0xffffffffu, acc, k, 8);

    int cb = f * 8;
    float o[8];
#pragma unroll
    for (int j = 0; j < 8; j++) {
        float a = bs[cb + j];
#pragma unroll
        for (int k = 0; k < 5; k++) a += v[k] * Ws[k * 64 + cb + j];
        o[j] = fmaxf(a, 0.f) * ds;
    }
    if (live) {
        __half2 q0 = __float22half2_rn(make_float2(o[0], o[1]));
        __half2 q1 = __float22half2_rn(make_float2(o[2], o[3]));
        __half2 q2 = __float22half2_rn(make_float2(o[4], o[5]));
        __half2 q3 = __float22half2_rn(make_float2(o[6], o[7]));
        uint4 u;
        u.x = *(uint32_t*)&q0; u.y = *(uint32_t*)&q1;
        u.z = *(uint32_t*)&q2; u.w = *(uint32_t*)&q3;
        *reinterpret_cast<uint4*>(&out[(size_t)node * 64 + cb]) = u;
    }
}

// ---------------- agg width 64 on fp16: warp/node, half2 loads, 4x unroll ----
// lane q handles feature pair (2q, 2q+1). h prescaled by dinv[src].
template <bool POOL>
__global__ void k_agg64h(const __half2* __restrict__ h,
                         const int* __restrict__ rowptr, const int* __restrict__ col,
                         const float* __restrict__ dinv,
                         const float* __restrict__ bias,
                         const void* __restrict__ batch, const int* flag,
                         float* __restrict__ out, float* pool, float* gcnt, int n) {
    int node = blockIdx.x * 8 + (threadIdx.x >> 5);
    int lane = threadIdx.x & 31;
    if (node >= n) return;
    int beg = rowptr[node], end = rowptr[node + 1];
    float a0 = 0.f, a1 = 0.f;
    int e = beg;
    for (; e + 3 < end; e += 4) {
        int s0 = col[e], s1 = col[e + 1], s2 = col[e + 2], s3 = col[e + 3];
        __half2 v0 = __ldg(&h[(size_t)s0 * 32 + lane]);
        __half2 v1 = __ldg(&h[(size_t)s1 * 32 + lane]);
        __half2 v2 = __ldg(&h[(size_t)s2 * 32 + lane]);
        __half2 v3 = __ldg(&h[(size_t)s3 * 32 + lane]);
        float2 f0 = __half22float2(v0);
        float2 f1 = __half22float2(v1);
        float2 f2 = __half22float2(v2);
        float2 f3 = __half22float2(v3);
        a0 += (f0.x + f1.x) + (f2.x + f3.x);
        a1 += (f0.y + f1.y) + (f2.y + f3.y);
    }
    for (; e < end; e++) {
        int s = col[e];
        float2 f = __half22float2(__ldg(&h[(size_t)s * 32 + lane]));
        a0 += f.x;
        a1 += f.y;
    }
    float2 self = __half22float2(h[(size_t)node * 32 + lane]);
    float ds = dinv[node];
    a0 = ds * (a0 + self.x);
    a1 = ds * (a1 + self.y);
    if (POOL) {
        a0 = fmaxf(a0 + __ldg(&bias[2 * lane]), 0.f);
        a1 = fmaxf(a1 + __ldg(&bias[2 * lane + 1]), 0.f);
        int g = load_idx(batch, node, flag[0]);
        atomicAdd(&pool[g * 64 + 2 * lane], a0);
        atomicAdd(&pool[g * 64 + 2 * lane + 1], a1);
        if (lane == 0) atomicAdd(&gcnt[g], 1.0f);
    } else {
        *reinterpret_cast<float2*>(&out[(size_t)node * 64 + 2 * lane]) =
            make_float2(a0, a1);
    }
}

// ---------------- mma.sync bf16 split GEMM: 128-row tile, 8 warps ----------
// HALFOUT: store output as fp16 (gather array), else fp32.
template <int K, int NC, bool RELU, bool SCALE, bool HALFOUT>
__launch_bounds__(256)
__global__ void k_gemm_mma(const float* __restrict__ A, const float* __restrict__ W,
                           const float* __restrict__ bias, const float* __restrict__ dinv,
                           void* __restrict__ outv, int n) {
    constexpr int P = K + 8;
    extern __shared__ char sm[];
    uint16_t* Ah = (uint16_t*)sm;              // [128][P]
    uint16_t* Al = Ah + 128 * P;
    uint16_t* Bh = Al + 128 * P;               // [NC][P]
    uint16_t* Bl = Bh + NC * P;

    const int tid = threadIdx.x;
    const int nodeBase = blockIdx.x * 128;

    for (int q = tid; q < 128 * (K / 2); q += 256) {
        int r = q / (K / 2);
        int c2 = (q % (K / 2)) * 2;
        int gn = nodeBase + r;
        float2 v = (gn < n) ? *reinterpret_cast<const float2*>(&A[(size_t)gn * K + c2])
                            : make_float2(0.f, 0.f);
        uint32_t h, l;
        split2(v.x, v.y, h, l);
        *(uint32_t*)&Ah[r * P + c2] = h;
        *(uint32_t*)&Al[r * P + c2] = l;
    }
    for (int q = tid; q < NC * (K / 2); q += 256) {
        int nrow = q % NC;
        int k2 = (q / NC) * 2;
        float a = __ldg(&W[(size_t)k2 * NC + nrow]);
        float b = __ldg(&W[(size_t)(k2 + 1) * NC + nrow]);
        uint32_t h, l;
        split2(a, b, h, l);
        *(uint32_t*)&Bh[nrow * P + k2] = h;
        *(uint32_t*)&Bl[nrow * P + k2] = l;
    }
    __syncthreads();

    const int wid = tid >> 5;
    const int lane = tid & 31;
    const int g = lane >> 2;
    const int t4 = lane & 3;
    const int warpRow = wid * 16;

    float acc[NC / 8][4];
#pragma unroll
    for (int nt = 0; nt < NC / 8; nt++)
#pragma unroll
        for (int j = 0; j < 4; j++) acc[nt][j] = 0.f;

#pragma unroll
    for (int ks = 0; ks < K / 16; ks++) {
        int k0 = ks * 16;
        int r0 = warpRow + g;
        uint32_t ah[4], al[4];
        ah[0] = *(uint32_t*)&Ah[r0 * P + k0 + 2 * t4];
        ah[1] = *(uint32_t*)&Ah[(r0 + 8) * P + k0 + 2 * t4];
        ah[2] = *(uint32_t*)&Ah[r0 * P + k0 + 2 * t4 + 8];
        ah[3] = *(uint32_t*)&Ah[(r0 + 8) * P + k0 + 2 * t4 + 8];
        al[0] = *(uint32_t*)&Al[r0 * P + k0 + 2 * t4];
        al[1] = *(uint32_t*)&Al[(r0 + 8) * P + k0 + 2 * t4];
        al[2] = *(uint32_t*)&Al[r0 * P + k0 + 2 * t4 + 8];
        al[3] = *(uint32_t*)&Al[(r0 + 8) * P + k0 + 2 * t4 + 8];
#pragma unroll
        for (int nt = 0; nt < NC / 8; nt++) {
            int nr = nt * 8 + g;
            uint32_t bh0 = *(uint32_t*)&Bh[nr * P + k0 + 2 * t4];
            uint32_t bh1 = *(uint32_t*)&Bh[nr * P + k0 + 2 * t4 + 8];
            uint32_t bl0 = *(uint32_t*)&Bl[nr * P + k0 + 2 * t4];
            uint32_t bl1 = *(uint32_t*)&Bl[nr * P + k0 + 2 * t4 + 8];
            mma16816(acc[nt], ah, bh0, bh1);
            mma16816(acc[nt], ah, bl0, bl1);
            mma16816(acc[nt], al, bh0, bh1);
        }
    }

    int row0 = nodeBase + warpRow + g;
    int row1 = row0 + 8;
    bool l0 = row0 < n, l1 = row1 < n;
    float ds0 = (SCALE && l0) ? dinv[row0] : 1.0f;
    float ds1 = (SCALE && l1) ? dinv[row1] : 1.0f;
#pragma unroll
    for (int nt = 0; nt < NC / 8; nt++) {
        int colc = nt * 8 + 2 * t4;
        float b0 = RELU ? __ldg(&bias[colc]) : 0.f;
        float b1 = RELU ? __ldg(&bias[colc + 1]) : 0.f;
        float v0 = acc[nt][0], v1 = acc[nt][1], v2 = acc[nt][2], v3 = acc[nt][3];
        if (RELU) {
            v0 = fmaxf(v0 + b0, 0.f); v1 = fmaxf(v1 + b1, 0.f);
            v2 = fmaxf(v2 + b0, 0.f); v3 = fmaxf(v3 + b1, 0.f);
        }
        if (SCALE) { v0 *= ds0; v1 *= ds0; v2 *= ds1; v3 *= ds1; }
        if (HALFOUT) {
            __half* out = (__half*)outv;
            if (l0) {
                __half2 hh = __float22half2_rn(make_float2(v0, v1));
                *(uint32_t*)&out[(size_t)row0 * NC + colc] = *(uint32_t*)&hh;
            }
            if (l1) {
                __half2 hh = __float22half2_rn(make_float2(v2, v3));
                *(uint32_t*)&out[(size_t)row1 * NC + colc] = *(uint32_t*)&hh;
            }
        } else {
            float* out = (float*)outv;
            if (l0) *reinterpret_cast<float2*>(&out[(size_t)row0 * NC + colc]) = make_float2(v0, v1);
            if (l1) *reinterpret_cast<float2*>(&out[(size_t)row1 * NC + colc]) = make_float2(v2, v3);
        }
    }
}

// ---------------- final FC + sigmoid ----------------
__global__ void k_final(const float* __restrict__ pool, const float* __restrict__ gcnt,
                        const float* __restrict__ Wfc, const float* __restrict__ bfc,
                        float* __restrict__ out) {
    int g = threadIdx.x;
    float c = fmaxf(gcnt[g], 1.0f);
    float acc = 0.f;
#pragma unroll
    for (int k = 0; k < 64; k++) acc += pool[g * 64 + k] * Wfc[k];
    acc = acc / c + bfc[0];
    out[g] = 1.f / (1.f + expf(-acc));
}

// ---------------- launch ----------------
extern "C" void kernel_launch(void* const* d_in, const int* in_sizes, int n_in,
                              void* d_out, int out_size) {
    const float*  x     = (const float*)d_in[0];
    const void*   ei    = d_in[1];
    const void*   batch = d_in[2];
    const float*  W1    = (const float*)d_in[3];
    const float*  b1    = (const float*)d_in[4];
    const float*  W2    = (const float*)d_in[5];
    const float*  b2    = (const float*)d_in[6];
    const float*  W3    = (const float*)d_in[7];
    const float*  b3    = (const float*)d_in[8];
    const float*  Wfc   = (const float*)d_in[9];
    const float*  bfc   = (const float*)d_in[10];
    float*        out   = (float*)d_out;

    const int N = in_sizes[0] / 5;
    const int E = in_sizes[1] / 2;

    float *bufA, *bufB, *xs, *dinv, *pool, *gcnt;
    __half *h1, *h3;
    int *cnt, *rowptr, *curoff, *col, *bsums, *is64;
    cudaGetSymbolAddress((void**)&bufA, g_bufA);
    cudaGetSymbolAddress((void**)&bufB, g_bufB);
    cudaGetSymbolAddress((void**)&h1, g_h1);
    cudaGetSymbolAddress((void**)&h3, g_h3);
    cudaGetSymbolAddress((void**)&xs, g_xs);
    cudaGetSymbolAddress((void**)&dinv, g_dinv);
    cudaGetSymbolAddress((void**)&pool, g_pool);
    cudaGetSymbolAddress((void**)&gcnt, g_gcnt);
    cudaGetSymbolAddress((void**)&cnt, g_cnt);
    cudaGetSymbolAddress((void**)&rowptr, g_rowptr);
    cudaGetSymbolAddress((void**)&curoff, g_curoff);
    cudaGetSymbolAddress((void**)&col, g_col);
    cudaGetSymbolAddress((void**)&bsums, g_bsums);
    cudaGetSymbolAddress((void**)&is64, g_is64);

    const int SM2 = (128 + 128) * (64 + 8) * 2 * 2;
    const int SM3 = (128 + 64) * (128 + 8) * 2 * 2;
    static int smem_set = 0;
    if (!smem_set) {
        cudaFuncSetAttribute(k_gemm_mma<64, 128, true, false, false>,
                             cudaFuncAttributeMaxDynamicSharedMemorySize, SM2);
        cudaFuncSetAttribute(k_gemm_mma<128, 64, false, true, true>,
                             cudaFuncAttributeMaxDynamicSharedMemorySize, SM3);
        smem_set = 1;
    }

    const int TB = 256;
    int initN = N > NGRAPH * 64 ? N : NGRAPH * 64;
    k_init<<<(initN + TB - 1) / TB, TB>>>(cnt, pool, gcnt, N, (const int*)ei, is64);
    k_count<<<(E + TB - 1) / TB, TB>>>(ei, E, cnt, is64);

    int nb = (N + 1023) / 1024;
    k_scan1<<<nb, 1024>>>(cnt, rowptr, bsums, N);
    k_scan2<<<1, 128>>>(bsums, nb);
    k_scan3<<<(N + TB - 1) / TB, TB>>>(rowptr, curoff, bsums, cnt, dinv, x, xs, N, E);
    k_fill<<<(E + TB - 1) / TB, TB>>>(ei, E, curoff, col, is64);

    // L1 fused: agg5 + GEMM(5->64) + relu, prescaled -> h1 (fp16)
    k_l1<<<(N * 8 + TB - 1) / TB, TB>>>(xs, rowptr, col, dinv, W1, b1, h1, N);

    // L2: fp16 agg -> bufB (fp32); mma GEMM(64->128)+b2+relu -> bufA (fp32)
    k_agg64h<false><<<(N + 7) / 8, TB>>>((const __half2*)h1, rowptr, col, dinv,
                                         nullptr, nullptr, is64, bufB,
                                         nullptr, nullptr, N);
    int gtc = (N + 127) / 128;
    k_gemm_mma<64, 128, true, false, false><<<gtc, 256, SM2>>>(bufB, W2, b2, nullptr, bufA, N);

    // L3: mma GEMM(128->64) *dinv -> h3 (fp16); fp16 agg + b3 + relu + pool
    k_gemm_mma<128, 64, false, true, true><<<gtc, 256, SM3>>>(bufA, W3, nullptr, dinv, h3, N);
    k_agg64h<true><<<(N + 7) / 8, TB>>>((const __half2*)h3, rowptr, col, dinv, b3,
                                        batch, is64, nullptr, pool, gcnt, N);

    k_final<<<1, NGRAPH>>>(pool, gcnt, Wfc, bfc, out);
}